// round 1
// baseline (speedup 1.0000x reference)
#include <cuda_runtime.h>
#include <math.h>

#define BQ 512
#define II 2048
#define HH 2048
#define NELEM (BQ * HH)

// 16 MB scratch for the 4 gate preactivations (i, f, g, c~)
__device__ float g_preact[4][NELEM];

// ---------------------------------------------------------------------------
// Fused gate GEMM: preact[g] = X @ W[g] + S0 @ U[g] + b[g]
// Tile: 64(B) x 64(H), BK=16, 256 threads, 4x4 per thread, fp32 FFMA.
// grid = (HH/64, BQ/64, 4 gates)
// ---------------------------------------------------------------------------
__global__ __launch_bounds__(256, 2) void gate_gemm(
    const float* __restrict__ X, const float* __restrict__ S0,
    const float* __restrict__ W0, const float* __restrict__ U0, const float* __restrict__ b0,
    const float* __restrict__ W1, const float* __restrict__ U1, const float* __restrict__ b1,
    const float* __restrict__ W2, const float* __restrict__ U2, const float* __restrict__ b2,
    const float* __restrict__ W3, const float* __restrict__ U3, const float* __restrict__ b3)
{
    const float* Wg[4] = {W0, W1, W2, W3};
    const float* Ug[4] = {U0, U1, U2, U3};
    const float* bg[4] = {b0, b1, b2, b3};

    const int gate = blockIdx.z;
    const float* __restrict__ W = Wg[gate];
    const float* __restrict__ U = Ug[gate];
    const float* __restrict__ bias = bg[gate];

    __shared__ float As[16][64];   // [k][m]
    __shared__ float Bs[16][64];   // [k][n]

    const int row0 = blockIdx.y * 64;
    const int col0 = blockIdx.x * 64;
    const int t  = threadIdx.x;
    const int tx = t & 15;         // 0..15 -> col group
    const int ty = t >> 4;         // 0..15 -> row group

    // A loader: thread loads one float4 along K.  row = t/4 (0..63), kq = (t%4)*4
    const int la_row = t >> 2;
    const int la_k   = (t & 3) * 4;
    // B loader: thread loads one float4 along N.  kr = t/16 (0..15), cq = (t%16)*4
    const int lb_k   = t >> 4;
    const int lb_c   = (t & 15) * 4;

    float acc[4][4] = {};

    // Virtual K = 4096: first half X/W, second half S0/U.
    for (int kk = 0; kk < II + HH; kk += 16) {
        const float* __restrict__ Asrc;
        const float* __restrict__ Bsrc;
        int ks;
        if (kk < II) { Asrc = X;  Bsrc = W; ks = kk; }
        else         { Asrc = S0; Bsrc = U; ks = kk - II; }

        // load A tile (transposed into As[k][m])
        float4 av = *reinterpret_cast<const float4*>(
            &Asrc[(size_t)(row0 + la_row) * II + ks + la_k]);
        As[la_k + 0][la_row] = av.x;
        As[la_k + 1][la_row] = av.y;
        As[la_k + 2][la_row] = av.z;
        As[la_k + 3][la_row] = av.w;

        // load B tile
        float4 bv = *reinterpret_cast<const float4*>(
            &Bsrc[(size_t)(ks + lb_k) * HH + col0 + lb_c]);
        *reinterpret_cast<float4*>(&Bs[lb_k][lb_c]) = bv;

        __syncthreads();

        #pragma unroll
        for (int k = 0; k < 16; k++) {
            float4 a = *reinterpret_cast<const float4*>(&As[k][ty * 4]);
            float4 b = *reinterpret_cast<const float4*>(&Bs[k][tx * 4]);
            float ar[4] = {a.x, a.y, a.z, a.w};
            float br[4] = {b.x, b.y, b.z, b.w};
            #pragma unroll
            for (int i = 0; i < 4; i++)
                #pragma unroll
                for (int j = 0; j < 4; j++)
                    acc[i][j] = fmaf(ar[i], br[j], acc[i][j]);
        }
        __syncthreads();
    }

    // epilogue: add bias, store preactivation
    float* __restrict__ out = g_preact[gate];
    #pragma unroll
    for (int i = 0; i < 4; i++) {
        int r = row0 + ty * 4 + i;
        #pragma unroll
        for (int j = 0; j < 4; j++) {
            int cidx = col0 + tx * 4 + j;
            out[(size_t)r * HH + cidx] = acc[i][j] + bias[cidx];
        }
    }
}

// ---------------------------------------------------------------------------
// Elementwise gates + output assembly.
// mode 0: out = c                    (out_size ==   B*H)
// mode 1: out = [state, c]           (out_size == 2*B*H)
// mode 2: out = [c, state, c]        (out_size == 3*B*H)
// ---------------------------------------------------------------------------
__device__ __forceinline__ float sigmoidf_(float x) {
    return 1.0f / (1.0f + __expf(-x));
}

__global__ __launch_bounds__(256) void lstm_elem(
    const float* __restrict__ prevoutput, float* __restrict__ out, int mode)
{
    int idx = blockIdx.x * blockDim.x + threadIdx.x;
    if (idx >= NELEM) return;

    float gi = sigmoidf_(g_preact[0][idx]);
    float gf = sigmoidf_(g_preact[1][idx]);
    float gg = sigmoidf_(g_preact[2][idx]);
    float gc = tanhf(g_preact[3][idx]);

    float c  = gf * prevoutput[idx] + gi * gc;
    float st = gg * tanhf(c);

    if (mode == 0) {
        out[idx] = c;
    } else if (mode == 1) {
        out[idx]          = st;
        out[NELEM + idx]  = c;
    } else {
        out[idx]              = c;
        out[NELEM + idx]      = st;
        out[2 * NELEM + idx]  = c;
    }
}

// ---------------------------------------------------------------------------
extern "C" void kernel_launch(void* const* d_in, const int* in_sizes, int n_in,
                              void* d_out, int out_size)
{
    const float* X      = (const float*)d_in[0];
    const float* states = (const float*)d_in[1];
    const float* S0 = states;            // prevstate
    const float* S1 = states + NELEM;    // prevoutput

    const float* Wi = (const float*)d_in[2];
    const float* Ui = (const float*)d_in[3];
    const float* bi = (const float*)d_in[4];
    const float* Wf = (const float*)d_in[5];
    const float* Uf = (const float*)d_in[6];
    const float* bf = (const float*)d_in[7];
    const float* Wg = (const float*)d_in[8];
    const float* Ug = (const float*)d_in[9];
    const float* bg = (const float*)d_in[10];
    const float* Wc = (const float*)d_in[11];
    const float* Uc = (const float*)d_in[12];
    const float* bc = (const float*)d_in[13];

    dim3 grid(HH / 64, BQ / 64, 4);
    gate_gemm<<<grid, 256>>>(X, S0,
                             Wi, Ui, bi,
                             Wf, Uf, bf,
                             Wg, Ug, bg,
                             Wc, Uc, bc);

    int mode;
    if (out_size == NELEM)           mode = 0;
    else if (out_size == 2 * NELEM)  mode = 1;
    else                             mode = 2;

    lstm_elem<<<(NELEM + 255) / 256, 256>>>(S1, (float*)d_out, mode);
}

// round 3
// speedup vs baseline: 4.4196x; 4.4196x over previous
#include <cuda_runtime.h>
#include <cstdint>
#include <math.h>

#define BQ 512
#define II 2048
#define HH 2048
#define NELEM (BQ * HH)

#define BM 128
#define BN 256
#define BK 32
#define STAGES 3
#define NITER 128          // 4096 / 32

// A stage: [128][36] floats, B stage: [32][260] floats
#define A_LDS   36
#define B_LDS   260
#define A_STAGE_F (BM * A_LDS)          // 4608 floats
#define B_STAGE_F (BK * B_LDS)          // 8320 floats
#define SMEM_BYTES ((STAGES * (A_STAGE_F + B_STAGE_F)) * 4)   // 155136

// 16 MB scratch for the 4 gate preactivations
__device__ float g_preact[4][NELEM];

// ---------------------------------------------------------------------------
__device__ __forceinline__ uint32_t smem_u32(const void* p) {
    uint32_t a;
    asm("{ .reg .u64 t; cvta.to.shared.u64 t, %1; cvt.u32.u64 %0, t; }" : "=r"(a) : "l"(p));
    return a;
}
__device__ __forceinline__ void cpasync16(uint32_t dst, const void* src) {
    asm volatile("cp.async.cg.shared.global [%0], [%1], 16;" :: "r"(dst), "l"(src));
}
#define CP_COMMIT() asm volatile("cp.async.commit_group;" ::: "memory")
#define CP_WAIT(n)  asm volatile("cp.async.wait_group %0;" :: "n"(n) : "memory")

__device__ __forceinline__ uint32_t f2tf32(float f) {
    uint32_t r; asm("cvt.rna.tf32.f32 %0, %1;" : "=r"(r) : "f"(f)); return r;
}
__device__ __forceinline__ void mma16n8k8(float* c, const uint32_t* a, const uint32_t* b) {
    asm volatile(
        "mma.sync.aligned.m16n8k8.row.col.f32.tf32.tf32.f32 "
        "{%0,%1,%2,%3}, {%4,%5,%6,%7}, {%8,%9}, {%0,%1,%2,%3};"
        : "+f"(c[0]), "+f"(c[1]), "+f"(c[2]), "+f"(c[3])
        : "r"(a[0]), "r"(a[1]), "r"(a[2]), "r"(a[3]), "r"(b[0]), "r"(b[1]));
}

// ---------------------------------------------------------------------------
// Fused gate GEMM on tensor cores (tf32 mma.sync):
//   g_preact[gate] = X @ W_gate + S0 @ U_gate + bias_gate
// grid (4 Mtiles, 8 Ntiles, 4 gates), 256 threads, BM=128 BN=256 BK=32.
// ---------------------------------------------------------------------------
__global__ __launch_bounds__(256, 1) void gate_gemm_tc(
    const float* __restrict__ X, const float* __restrict__ S0,
    const float* __restrict__ W0, const float* __restrict__ U0, const float* __restrict__ b0,
    const float* __restrict__ W1, const float* __restrict__ U1, const float* __restrict__ b1,
    const float* __restrict__ W2, const float* __restrict__ U2, const float* __restrict__ b2,
    const float* __restrict__ W3, const float* __restrict__ U3, const float* __restrict__ b3)
{
    extern __shared__ float smem[];
    float* As = smem;                              // [STAGES][128][36]
    float* Bs = smem + STAGES * A_STAGE_F;         // [STAGES][32][260]
    const uint32_t asA = smem_u32(As);
    const uint32_t asB = smem_u32(Bs);

    const int tid  = threadIdx.x;
    const int lane = tid & 31;
    const int warp = tid >> 5;
    const int wm   = (warp & 1) * 64;      // warp offset in M
    const int wn   = (warp >> 1) * 64;     // warp offset in N

    const int m0 = blockIdx.x * BM;
    const int n0 = blockIdx.y * BN;
    const int gate = blockIdx.z;

    const float* W = (gate == 0) ? W0 : (gate == 1) ? W1 : (gate == 2) ? W2 : W3;
    const float* U = (gate == 0) ? U0 : (gate == 1) ? U1 : (gate == 2) ? U2 : U3;
    const float* bias = (gate == 0) ? b0 : (gate == 1) ? b1 : (gate == 2) ? b2 : b3;

    // loader indices
    const int a_row = tid >> 3;            // + t*32
    const int a_kc  = (tid & 7) * 4;
    const int b_kr  = tid >> 6;            // + t*4
    const int b_nc  = (tid & 63) * 4;

    float acc[4][8][4];
    #pragma unroll
    for (int mt = 0; mt < 4; mt++)
        #pragma unroll
        for (int nt = 0; nt < 8; nt++)
            #pragma unroll
            for (int q = 0; q < 4; q++) acc[mt][nt][q] = 0.0f;

    // ---- issue one chunk's loads into stage s ----
    auto load_chunk = [&](int i, int s) {
        const float* Ag = (i < 64) ? X : S0;
        const float* Bg = (i < 64) ? W : U;
        const int kb = (i & 63) * BK;
        const uint32_t aofs = asA + (uint32_t)s * (A_STAGE_F * 4);
        const uint32_t bofs = asB + (uint32_t)s * (B_STAGE_F * 4);
        #pragma unroll
        for (int t = 0; t < 4; t++) {
            const int row = a_row + t * 32;
            cpasync16(aofs + (uint32_t)(row * A_LDS + a_kc) * 4,
                      Ag + (size_t)(m0 + row) * II + kb + a_kc);
        }
        #pragma unroll
        for (int t = 0; t < 8; t++) {
            const int kr = b_kr + t * 4;
            cpasync16(bofs + (uint32_t)(kr * B_LDS + b_nc) * 4,
                      Bg + (size_t)(kb + kr) * HH + n0 + b_nc);
        }
    };

    // prologue: stages 0 .. STAGES-2
    #pragma unroll
    for (int s = 0; s < STAGES - 1; s++) { load_chunk(s, s); CP_COMMIT(); }

    for (int i = 0; i < NITER; i++) {
        CP_WAIT(STAGES - 2);
        __syncthreads();

        // prefetch chunk i+STAGES-1 into stage (i+STAGES-1)%STAGES
        if (i + STAGES - 1 < NITER)
            load_chunk(i + STAGES - 1, (i + STAGES - 1) % STAGES);
        CP_COMMIT();

        const int s = i % STAGES;
        const float* Asb = As + s * A_STAGE_F;
        const float* Bsb = Bs + s * B_STAGE_F;

        #pragma unroll
        for (int ks = 0; ks < 4; ks++) {
            const int k = ks * 8;
            uint32_t a[4][4], b[8][2];
            #pragma unroll
            for (int mt = 0; mt < 4; mt++) {
                const int r = wm + mt * 16 + (lane >> 2);
                const int c = k + (lane & 3);
                a[mt][0] = f2tf32(Asb[r * A_LDS + c]);
                a[mt][1] = f2tf32(Asb[(r + 8) * A_LDS + c]);
                a[mt][2] = f2tf32(Asb[r * A_LDS + c + 4]);
                a[mt][3] = f2tf32(Asb[(r + 8) * A_LDS + c + 4]);
            }
            #pragma unroll
            for (int nt = 0; nt < 8; nt++) {
                const int kr = k + (lane & 3);
                const int cc = wn + nt * 8 + (lane >> 2);
                b[nt][0] = f2tf32(Bsb[kr * B_LDS + cc]);
                b[nt][1] = f2tf32(Bsb[(kr + 4) * B_LDS + cc]);
            }
            #pragma unroll
            for (int mt = 0; mt < 4; mt++)
                #pragma unroll
                for (int nt = 0; nt < 8; nt++)
                    mma16n8k8(acc[mt][nt], a[mt], b[nt]);
        }
        __syncthreads();
    }

    // ---- epilogue: bias + store ----
    float* __restrict__ outp = g_preact[gate];
    #pragma unroll
    for (int mt = 0; mt < 4; mt++) {
        const int r0 = m0 + wm + mt * 16 + (lane >> 2);
        #pragma unroll
        for (int nt = 0; nt < 8; nt++) {
            const int cidx = n0 + wn + nt * 8 + (lane & 3) * 2;
            const float bx = __ldg(&bias[cidx]);
            const float by = __ldg(&bias[cidx + 1]);
            float2 v0 = make_float2(acc[mt][nt][0] + bx, acc[mt][nt][1] + by);
            float2 v1 = make_float2(acc[mt][nt][2] + bx, acc[mt][nt][3] + by);
            *reinterpret_cast<float2*>(&outp[(size_t)r0 * HH + cidx]) = v0;
            *reinterpret_cast<float2*>(&outp[(size_t)(r0 + 8) * HH + cidx]) = v1;
        }
    }
}

// ---------------------------------------------------------------------------
// Elementwise gates + output assembly (float4 vectorized).
// ---------------------------------------------------------------------------
__device__ __forceinline__ float sigf(float x) { return 1.0f / (1.0f + __expf(-x)); }

__global__ __launch_bounds__(256) void lstm_elem(
    const float* __restrict__ prevoutput, float* __restrict__ out, int mode)
{
    int i = blockIdx.x * blockDim.x + threadIdx.x;
    if (i >= NELEM / 4) return;
    float4 pa = reinterpret_cast<const float4*>(g_preact[0])[i];
    float4 pb = reinterpret_cast<const float4*>(g_preact[1])[i];
    float4 pc = reinterpret_cast<const float4*>(g_preact[2])[i];
    float4 pd = reinterpret_cast<const float4*>(g_preact[3])[i];
    float4 po = reinterpret_cast<const float4*>(prevoutput)[i];

    float4 c, st;
    {
        float gi = sigf(pa.x), gf = sigf(pb.x), gg = sigf(pc.x), gc = tanhf(pd.x);
        c.x = gf * po.x + gi * gc; st.x = gg * tanhf(c.x);
        gi = sigf(pa.y); gf = sigf(pb.y); gg = sigf(pc.y); gc = tanhf(pd.y);
        c.y = gf * po.y + gi * gc; st.y = gg * tanhf(c.y);
        gi = sigf(pa.z); gf = sigf(pb.z); gg = sigf(pc.z); gc = tanhf(pd.z);
        c.z = gf * po.z + gi * gc; st.z = gg * tanhf(c.z);
        gi = sigf(pa.w); gf = sigf(pb.w); gg = sigf(pc.w); gc = tanhf(pd.w);
        c.w = gf * po.w + gi * gc; st.w = gg * tanhf(c.w);
    }
    float4* o4 = reinterpret_cast<float4*>(out);
    const int Q = NELEM / 4;
    if (mode == 0) {
        o4[i] = c;
    } else if (mode == 1) {
        o4[i] = st; o4[Q + i] = c;
    } else {
        o4[i] = c; o4[Q + i] = st; o4[2 * Q + i] = c;
    }
}

// ---------------------------------------------------------------------------
extern "C" void kernel_launch(void* const* d_in, const int* in_sizes, int n_in,
                              void* d_out, int out_size)
{
    const float* X      = (const float*)d_in[0];
    const float* states = (const float*)d_in[1];
    const float* S0 = states;
    const float* S1 = states + NELEM;

    static bool attr_set = false;
    if (!attr_set) {
        cudaFuncSetAttribute(gate_gemm_tc,
                             cudaFuncAttributeMaxDynamicSharedMemorySize, SMEM_BYTES);
        attr_set = true;
    }

    dim3 grid(BQ / BM, HH / BN, 4);   // (4, 8, 4) — M fastest for L2 B reuse
    gate_gemm_tc<<<grid, 256, SMEM_BYTES>>>(
        X, S0,
        (const float*)d_in[2],  (const float*)d_in[3],  (const float*)d_in[4],
        (const float*)d_in[5],  (const float*)d_in[6],  (const float*)d_in[7],
        (const float*)d_in[8],  (const float*)d_in[9],  (const float*)d_in[10],
        (const float*)d_in[11], (const float*)d_in[12], (const float*)d_in[13]);

    int mode;
    if (out_size == NELEM)          mode = 0;
    else if (out_size == 2 * NELEM) mode = 1;
    else                            mode = 2;
    lstm_elem<<<NELEM / 4 / 256, 256>>>(S1, (float*)d_out, mode);
}

// round 5
// speedup vs baseline: 5.4712x; 1.2379x over previous
#include <cuda_runtime.h>
#include <cstdint>
#include <math.h>

#define BQ 512
#define II 2048
#define HH 2048
#define NELEM (BQ * HH)

#define BM 128
#define BN 256
#define BK 32
#define STAGES 3
#define NITER 128          // 4096 / 32

// A stage: [128][36] floats, B stage: [32][260] floats
#define A_LDS   36
#define B_LDS   260
#define A_STAGE_F (BM * A_LDS)          // 4608 floats
#define B_STAGE_F (BK * B_LDS)          // 8320 floats
#define SMEM_BYTES ((STAGES * (A_STAGE_F + B_STAGE_F)) * 4)   // 155136

// 16 MB scratch for the 4 gate preactivations
__device__ float g_preact[4][NELEM];

// ---------------------------------------------------------------------------
__device__ __forceinline__ uint32_t smem_u32(const void* p) {
    uint32_t a;
    asm("{ .reg .u64 t; cvta.to.shared.u64 t, %1; cvt.u32.u64 %0, t; }" : "=r"(a) : "l"(p));
    return a;
}
__device__ __forceinline__ void cpasync16(uint32_t dst, const void* src) {
    asm volatile("cp.async.cg.shared.global [%0], [%1], 16;" :: "r"(dst), "l"(src));
}
#define CP_COMMIT() asm volatile("cp.async.commit_group;" ::: "memory")
#define CP_WAIT(n)  asm volatile("cp.async.wait_group %0;" :: "n"(n) : "memory")

// pack two fp32 -> fp16x2 {lo, hi}
__device__ __forceinline__ uint32_t packh2(float lo, float hi) {
    uint32_t r; asm("cvt.rn.f16x2.f32 %0, %1, %2;" : "=r"(r) : "f"(hi), "f"(lo)); return r;
}
__device__ __forceinline__ void mma16n8k16(float* c, const uint32_t* a, const uint32_t* b) {
    asm volatile(
        "mma.sync.aligned.m16n8k16.row.col.f32.f16.f16.f32 "
        "{%0,%1,%2,%3}, {%4,%5,%6,%7}, {%8,%9}, {%0,%1,%2,%3};"
        : "+f"(c[0]), "+f"(c[1]), "+f"(c[2]), "+f"(c[3])
        : "r"(a[0]), "r"(a[1]), "r"(a[2]), "r"(a[3]), "r"(b[0]), "r"(b[1]));
}

// ---------------------------------------------------------------------------
// Fused gate GEMM on tensor cores (fp16 mma.sync, fp32 accumulate):
//   g_preact[gate] = X @ W_gate + S0 @ U_gate + bias_gate
// grid (4 Mtiles, 8 Ntiles, 4 gates), 256 threads, BM=128 BN=256 BK=32.
// ---------------------------------------------------------------------------
__global__ __launch_bounds__(256, 1) void gate_gemm_tc(
    const float* __restrict__ X, const float* __restrict__ S0,
    const float* __restrict__ W0, const float* __restrict__ U0, const float* __restrict__ b0,
    const float* __restrict__ W1, const float* __restrict__ U1, const float* __restrict__ b1,
    const float* __restrict__ W2, const float* __restrict__ U2, const float* __restrict__ b2,
    const float* __restrict__ W3, const float* __restrict__ U3, const float* __restrict__ b3)
{
    extern __shared__ float smem[];
    float* As = smem;                              // [STAGES][128][36]
    float* Bs = smem + STAGES * A_STAGE_F;         // [STAGES][32][260]
    const uint32_t asA = smem_u32(As);
    const uint32_t asB = smem_u32(Bs);

    const int tid  = threadIdx.x;
    const int lane = tid & 31;
    const int warp = tid >> 5;
    const int wm   = (warp & 1) * 64;      // warp offset in M
    const int wn   = (warp >> 1) * 64;     // warp offset in N

    const int m0 = blockIdx.x * BM;
    const int n0 = blockIdx.y * BN;
    const int gate = blockIdx.z;

    const float* W = (gate == 0) ? W0 : (gate == 1) ? W1 : (gate == 2) ? W2 : W3;
    const float* U = (gate == 0) ? U0 : (gate == 1) ? U1 : (gate == 2) ? U2 : U3;
    const float* bias = (gate == 0) ? b0 : (gate == 1) ? b1 : (gate == 2) ? b2 : b3;

    // loader indices
    const int a_row = tid >> 3;            // + t*32
    const int a_kc  = (tid & 7) * 4;
    const int b_kr  = tid >> 6;            // + t*4
    const int b_nc  = (tid & 63) * 4;

    float acc[4][8][4];
    #pragma unroll
    for (int mt = 0; mt < 4; mt++)
        #pragma unroll
        for (int nt = 0; nt < 8; nt++)
            #pragma unroll
            for (int q = 0; q < 4; q++) acc[mt][nt][q] = 0.0f;

    // ---- issue one chunk's loads into stage s ----
    auto load_chunk = [&](int i, int s) {
        const float* Ag = (i < 64) ? X : S0;
        const float* Bg = (i < 64) ? W : U;
        const int kb = (i & 63) * BK;
        const uint32_t aofs = asA + (uint32_t)s * (A_STAGE_F * 4);
        const uint32_t bofs = asB + (uint32_t)s * (B_STAGE_F * 4);
        #pragma unroll
        for (int t = 0; t < 4; t++) {
            const int row = a_row + t * 32;
            cpasync16(aofs + (uint32_t)(row * A_LDS + a_kc) * 4,
                      Ag + (size_t)(m0 + row) * II + kb + a_kc);
        }
        #pragma unroll
        for (int t = 0; t < 8; t++) {
            const int kr = b_kr + t * 4;
            cpasync16(bofs + (uint32_t)(kr * B_LDS + b_nc) * 4,
                      Bg + (size_t)(kb + kr) * HH + n0 + b_nc);
        }
    };

    // prologue: stages 0 .. STAGES-2
    #pragma unroll
    for (int s = 0; s < STAGES - 1; s++) { load_chunk(s, s); CP_COMMIT(); }

    for (int i = 0; i < NITER; i++) {
        CP_WAIT(STAGES - 2);
        __syncthreads();

        // prefetch chunk i+STAGES-1 into stage (i+STAGES-1)%STAGES
        if (i + STAGES - 1 < NITER)
            load_chunk(i + STAGES - 1, (i + STAGES - 1) % STAGES);
        CP_COMMIT();

        const int s = i % STAGES;
        const float* Asb = As + s * A_STAGE_F;
        const float* Bsb = Bs + s * B_STAGE_F;

        // two K=16 steps per BK=32 chunk
        #pragma unroll
        for (int ks = 0; ks < 2; ks++) {
            const int k = ks * 16;
            uint32_t a[4][4], b[8][2];

            // A fragments: row-major fp32 smem, k contiguous -> float2 + pack
            #pragma unroll
            for (int mt = 0; mt < 4; mt++) {
                const int r  = wm + mt * 16 + (lane >> 2);
                const int kc = k + (lane & 3) * 2;
                float2 v0 = *reinterpret_cast<const float2*>(&Asb[r * A_LDS + kc]);
                float2 v1 = *reinterpret_cast<const float2*>(&Asb[(r + 8) * A_LDS + kc]);
                float2 v2 = *reinterpret_cast<const float2*>(&Asb[r * A_LDS + kc + 8]);
                float2 v3 = *reinterpret_cast<const float2*>(&Asb[(r + 8) * A_LDS + kc + 8]);
                a[mt][0] = packh2(v0.x, v0.y);
                a[mt][1] = packh2(v1.x, v1.y);
                a[mt][2] = packh2(v2.x, v2.y);
                a[mt][3] = packh2(v3.x, v3.y);
            }
            // B fragments: [k][n] smem, k pairs from adjacent rows (conflict-free)
            #pragma unroll
            for (int nt = 0; nt < 8; nt++) {
                const int kr = k + (lane & 3) * 2;
                const int cc = wn + nt * 8 + (lane >> 2);
                b[nt][0] = packh2(Bsb[kr * B_LDS + cc], Bsb[(kr + 1) * B_LDS + cc]);
                b[nt][1] = packh2(Bsb[(kr + 8) * B_LDS + cc], Bsb[(kr + 9) * B_LDS + cc]);
            }
            #pragma unroll
            for (int mt = 0; mt < 4; mt++)
                #pragma unroll
                for (int nt = 0; nt < 8; nt++)
                    mma16n8k16(acc[mt][nt], a[mt], b[nt]);
        }
        __syncthreads();
    }

    // ---- epilogue: bias + store ----
    float* __restrict__ outp = g_preact[gate];
    #pragma unroll
    for (int mt = 0; mt < 4; mt++) {
        const int r0 = m0 + wm + mt * 16 + (lane >> 2);
        #pragma unroll
        for (int nt = 0; nt < 8; nt++) {
            const int cidx = n0 + wn + nt * 8 + (lane & 3) * 2;
            const float bx = __ldg(&bias[cidx]);
            const float by = __ldg(&bias[cidx + 1]);
            float2 v0 = make_float2(acc[mt][nt][0] + bx, acc[mt][nt][1] + by);
            float2 v1 = make_float2(acc[mt][nt][2] + bx, acc[mt][nt][3] + by);
            *reinterpret_cast<float2*>(&outp[(size_t)r0 * HH + cidx]) = v0;
            *reinterpret_cast<float2*>(&outp[(size_t)(r0 + 8) * HH + cidx]) = v1;
        }
    }
}

// ---------------------------------------------------------------------------
// Elementwise gates + output assembly (float4 vectorized).
// ---------------------------------------------------------------------------
__device__ __forceinline__ float sigf(float x) { return 1.0f / (1.0f + __expf(-x)); }

__global__ __launch_bounds__(256) void lstm_elem(
    const float* __restrict__ prevoutput, float* __restrict__ out, int mode)
{
    int i = blockIdx.x * blockDim.x + threadIdx.x;
    if (i >= NELEM / 4) return;
    float4 pa = reinterpret_cast<const float4*>(g_preact[0])[i];
    float4 pb = reinterpret_cast<const float4*>(g_preact[1])[i];
    float4 pc = reinterpret_cast<const float4*>(g_preact[2])[i];
    float4 pd = reinterpret_cast<const float4*>(g_preact[3])[i];
    float4 po = reinterpret_cast<const float4*>(prevoutput)[i];

    float4 c, st;
    {
        float gi = sigf(pa.x), gf = sigf(pb.x), gg = sigf(pc.x), gc = tanhf(pd.x);
        c.x = gf * po.x + gi * gc; st.x = gg * tanhf(c.x);
        gi = sigf(pa.y); gf = sigf(pb.y); gg = sigf(pc.y); gc = tanhf(pd.y);
        c.y = gf * po.y + gi * gc; st.y = gg * tanhf(c.y);
        gi = sigf(pa.z); gf = sigf(pb.z); gg = sigf(pc.z); gc = tanhf(pd.z);
        c.z = gf * po.z + gi * gc; st.z = gg * tanhf(c.z);
        gi = sigf(pa.w); gf = sigf(pb.w); gg = sigf(pc.w); gc = tanhf(pd.w);
        c.w = gf * po.w + gi * gc; st.w = gg * tanhf(c.w);
    }
    float4* o4 = reinterpret_cast<float4*>(out);
    const int Q = NELEM / 4;
    if (mode == 0) {
        o4[i] = c;
    } else if (mode == 1) {
        o4[i] = st; o4[Q + i] = c;
    } else {
        o4[i] = c; o4[Q + i] = st; o4[2 * Q + i] = c;
    }
}

// ---------------------------------------------------------------------------
extern "C" void kernel_launch(void* const* d_in, const int* in_sizes, int n_in,
                              void* d_out, int out_size)
{
    const float* X      = (const float*)d_in[0];
    const float* states = (const float*)d_in[1];
    const float* S0 = states;
    const float* S1 = states + NELEM;

    static bool attr_set = false;
    if (!attr_set) {
        cudaFuncSetAttribute(gate_gemm_tc,
                             cudaFuncAttributeMaxDynamicSharedMemorySize, SMEM_BYTES);
        attr_set = true;
    }

    dim3 grid(BQ / BM, HH / BN, 4);   // (4, 8, 4) — M fastest for L2 B reuse
    gate_gemm_tc<<<grid, 256, SMEM_BYTES>>>(
        X, S0,
        (const float*)d_in[2],  (const float*)d_in[3],  (const float*)d_in[4],
        (const float*)d_in[5],  (const float*)d_in[6],  (const float*)d_in[7],
        (const float*)d_in[8],  (const float*)d_in[9],  (const float*)d_in[10],
        (const float*)d_in[11], (const float*)d_in[12], (const float*)d_in[13]);

    int mode;
    if (out_size == NELEM)          mode = 0;
    else if (out_size == 2 * NELEM) mode = 1;
    else                            mode = 2;
    lstm_elem<<<NELEM / 4 / 256, 256>>>(S1, (float*)d_out, mode);
}

// round 8
// speedup vs baseline: 5.9757x; 1.0922x over previous
#include <cuda_runtime.h>
#include <cuda_fp16.h>
#include <cstdint>
#include <math.h>

#define BQ 512
#define II 2048
#define HH 2048
#define NELEM (BQ * HH)

#define BM 128
#define BN 256
#define BK 64
#define STAGES 3
#define NITER 64           // 4096 / 64

// fp16 smem tiles, padded for conflict-free ldmatrix (+16B quad rotation/row)
#define A_LDS 72           // fp16 per A row  (64 data + 8 pad) = 144B
#define B_LDS 264          // fp16 per B row (256 data + 8 pad) = 528B
#define A_STAGE_B (BM * A_LDS * 2)     // 18432
#define B_STAGE_B (BK * B_LDS * 2)     // 33792
#define STAGE_B   (A_STAGE_B + B_STAGE_B)
#define SMEM_BYTES (STAGES * STAGE_B)  // 156672

// fp16 operand scratch + fp32 preactivation scratch
__device__ __half A_h[(size_t)BQ * 4096];              // 4 MB:  [m][k]  X | S0
__device__ __half B_h[(size_t)4 * 4096 * HH];          // 64 MB: [gate][k][n]  W | U
__device__ float  g_preact[4][NELEM];                  // 16 MB

// ---------------------------------------------------------------------------
__device__ __forceinline__ uint32_t smem_u32(const void* p) {
    uint32_t a;
    asm("{ .reg .u64 t; cvta.to.shared.u64 t, %1; cvt.u32.u64 %0, t; }" : "=r"(a) : "l"(p));
    return a;
}
__device__ __forceinline__ void cpasync16(uint32_t dst, const void* src) {
    asm volatile("cp.async.cg.shared.global [%0], [%1], 16;" :: "r"(dst), "l"(src));
}
#define CP_COMMIT() asm volatile("cp.async.commit_group;" ::: "memory")
#define CP_WAIT(n)  asm volatile("cp.async.wait_group %0;" :: "n"(n) : "memory")

__device__ __forceinline__ uint32_t packh2(float lo, float hi) {
    uint32_t r; asm("cvt.rn.f16x2.f32 %0, %1, %2;" : "=r"(r) : "f"(hi), "f"(lo)); return r;
}
__device__ __forceinline__ void ldsm_x4(uint32_t* r, uint32_t addr) {
    asm volatile("ldmatrix.sync.aligned.m8n8.x4.shared.b16 {%0,%1,%2,%3}, [%4];"
                 : "=r"(r[0]), "=r"(r[1]), "=r"(r[2]), "=r"(r[3]) : "r"(addr));
}
__device__ __forceinline__ void ldsm_x4_t(uint32_t* r, uint32_t addr) {
    asm volatile("ldmatrix.sync.aligned.m8n8.x4.trans.shared.b16 {%0,%1,%2,%3}, [%4];"
                 : "=r"(r[0]), "=r"(r[1]), "=r"(r[2]), "=r"(r[3]) : "r"(addr));
}
__device__ __forceinline__ void mma16n8k16(float* c, const uint32_t* a,
                                           uint32_t b0, uint32_t b1) {
    asm volatile(
        "mma.sync.aligned.m16n8k16.row.col.f32.f16.f16.f32 "
        "{%0,%1,%2,%3}, {%4,%5,%6,%7}, {%8,%9}, {%0,%1,%2,%3};"
        : "+f"(c[0]), "+f"(c[1]), "+f"(c[2]), "+f"(c[3])
        : "r"(a[0]), "r"(a[1]), "r"(a[2]), "r"(a[3]), "r"(b0), "r"(b1));
}

// ---------------------------------------------------------------------------
// fp32 -> fp16 convert kernels
// ---------------------------------------------------------------------------
struct WPtrs { const float* p[8]; };   // W0..W3, U0..U3

__global__ __launch_bounds__(256) void convert_B(WPtrs wp) {
    const size_t i  = (size_t)blockIdx.x * 256 + threadIdx.x;   // float4 index
    const size_t el = i * 4;
    const int gate = (int)(el >> 23);
    const int rem  = (int)(el & ((1u << 23) - 1));
    const int k = rem >> 11;
    const int n = rem & 2047;
    const float* src = (k < 2048)
        ? wp.p[gate]     + ((size_t)k << 11) + n
        : wp.p[4 + gate] + ((size_t)(k - 2048) << 11) + n;
    float4 v = *reinterpret_cast<const float4*>(src);
    uint2 o;
    o.x = packh2(v.x, v.y);
    o.y = packh2(v.z, v.w);
    reinterpret_cast<uint2*>(B_h)[i] = o;
}

__global__ __launch_bounds__(256) void convert_A(const float* __restrict__ X,
                                                 const float* __restrict__ S0) {
    const size_t i  = (size_t)blockIdx.x * 256 + threadIdx.x;
    const size_t el = i * 4;
    const int m = (int)(el >> 12);
    const int k = (int)(el & 4095);
    const float* src = (k < 2048) ? X  + ((size_t)m << 11) + k
                                  : S0 + ((size_t)m << 11) + (k - 2048);
    float4 v = *reinterpret_cast<const float4*>(src);
    uint2 o;
    o.x = packh2(v.x, v.y);
    o.y = packh2(v.z, v.w);
    reinterpret_cast<uint2*>(A_h)[i] = o;
}

// ---------------------------------------------------------------------------
// fp16 ldmatrix GEMM: g_preact[gate] = A_h @ B_h[gate] + bias
// grid (4 Mtiles, 8 Ntiles, 4 gates), 256 threads, BM=128 BN=256 BK=64.
// ---------------------------------------------------------------------------
__global__ __launch_bounds__(256, 1) void gate_gemm_tc(
    const float* __restrict__ b0, const float* __restrict__ b1,
    const float* __restrict__ b2, const float* __restrict__ b3)
{
    extern __shared__ char smem[];
    const uint32_t sbase = smem_u32(smem);

    const int tid  = threadIdx.x;
    const int lane = tid & 31;
    const int warp = tid >> 5;
    const int wm   = (warp & 1) * 64;
    const int wn   = (warp >> 1) * 64;

    const int m0 = blockIdx.x * BM;
    const int n0 = blockIdx.y * BN;
    const int gate = blockIdx.z;
    const __half* __restrict__ Bg = B_h + (size_t)gate * 4096 * HH;
    const float* bias = (gate == 0) ? b0 : (gate == 1) ? b1 : (gate == 2) ? b2 : b3;

    float acc[4][8][4];
    #pragma unroll
    for (int mt = 0; mt < 4; mt++)
        #pragma unroll
        for (int nt = 0; nt < 8; nt++)
            #pragma unroll
            for (int q = 0; q < 4; q++) acc[mt][nt][q] = 0.0f;

    // ---- async load of chunk i into stage s ----
    auto load_chunk = [&](int i, int s) {
        const int kb = i * BK;
        const uint32_t aofs = sbase + (uint32_t)s * STAGE_B;
        const uint32_t bofs = aofs + A_STAGE_B;
        #pragma unroll
        for (int j = 0; j < 4; j++) {             // A: 1024 16B-chunks
            const int c   = tid + 256 * j;
            const int row = c >> 3, cin = c & 7;
            cpasync16(aofs + (uint32_t)(row * A_LDS + cin * 8) * 2,
                      A_h + ((size_t)(m0 + row) << 12) + kb + cin * 8);
        }
        #pragma unroll
        for (int j = 0; j < 8; j++) {             // B: 2048 16B-chunks
            const int c   = tid + 256 * j;
            const int row = c >> 5, cin = c & 31;
            cpasync16(bofs + (uint32_t)(row * B_LDS + cin * 8) * 2,
                      Bg + ((size_t)(kb + row) << 11) + n0 + cin * 8);
        }
    };

    #pragma unroll
    for (int s = 0; s < STAGES - 1; s++) { load_chunk(s, s); CP_COMMIT(); }

    // per-thread invariant ldmatrix offsets
    const int lr = lane & 15;
    const int lh = lane >> 4;

    for (int i = 0; i < NITER; i++) {
        CP_WAIT(STAGES - 2);
        __syncthreads();

        if (i + STAGES - 1 < NITER)
            load_chunk(i + STAGES - 1, (i + STAGES - 1) % STAGES);
        CP_COMMIT();

        const int s = i % STAGES;
        const uint32_t aofs = sbase + (uint32_t)s * STAGE_B;
        const uint32_t bofs = aofs + A_STAGE_B;

        #pragma unroll
        for (int ks = 0; ks < 4; ks++) {
            const int k = ks * 16;
            uint32_t a[4][4], b[4][4];
            #pragma unroll
            for (int mt = 0; mt < 4; mt++)
                ldsm_x4(a[mt], aofs +
                        (uint32_t)((wm + mt * 16 + lr) * A_LDS + k + lh * 8) * 2);
            #pragma unroll
            for (int p = 0; p < 4; p++)
                ldsm_x4_t(b[p], bofs +
                          (uint32_t)((k + lr) * B_LDS + wn + p * 16 + lh * 8) * 2);
            #pragma unroll
            for (int mt = 0; mt < 4; mt++)
                #pragma unroll
                for (int p = 0; p < 4; p++) {
                    mma16n8k16(acc[mt][2 * p + 0], a[mt], b[p][0], b[p][1]);
                    mma16n8k16(acc[mt][2 * p + 1], a[mt], b[p][2], b[p][3]);
                }
        }
        __syncthreads();
    }

    // ---- epilogue: bias + store fp32 preactivations ----
    float* __restrict__ outp = g_preact[gate];
    #pragma unroll
    for (int mt = 0; mt < 4; mt++) {
        const int r0 = m0 + wm + mt * 16 + (lane >> 2);
        #pragma unroll
        for (int nt = 0; nt < 8; nt++) {
            const int cidx = n0 + wn + nt * 8 + (lane & 3) * 2;
            const float bx = __ldg(&bias[cidx]);
            const float by = __ldg(&bias[cidx + 1]);
            float2 v0 = make_float2(acc[mt][nt][0] + bx, acc[mt][nt][1] + by);
            float2 v1 = make_float2(acc[mt][nt][2] + bx, acc[mt][nt][3] + by);
            *reinterpret_cast<float2*>(&outp[(size_t)r0 * HH + cidx]) = v0;
            *reinterpret_cast<float2*>(&outp[(size_t)(r0 + 8) * HH + cidx]) = v1;
        }
    }
}

// ---------------------------------------------------------------------------
// Elementwise gates + output assembly (float4 vectorized).
// ---------------------------------------------------------------------------
__device__ __forceinline__ float sigf(float x) { return 1.0f / (1.0f + __expf(-x)); }

__global__ __launch_bounds__(256) void lstm_elem(
    const float* __restrict__ prevoutput, float* __restrict__ out, int mode)
{
    int i = blockIdx.x * blockDim.x + threadIdx.x;
    if (i >= NELEM / 4) return;
    float4 pa = reinterpret_cast<const float4*>(g_preact[0])[i];
    float4 pb = reinterpret_cast<const float4*>(g_preact[1])[i];
    float4 pc = reinterpret_cast<const float4*>(g_preact[2])[i];
    float4 pd = reinterpret_cast<const float4*>(g_preact[3])[i];
    float4 po = reinterpret_cast<const float4*>(prevoutput)[i];

    float4 c, st;
    {
        float gi = sigf(pa.x), gf = sigf(pb.x), gg = sigf(pc.x), gc = tanhf(pd.x);
        c.x = gf * po.x + gi * gc; st.x = gg * tanhf(c.x);
        gi = sigf(pa.y); gf = sigf(pb.y); gg = sigf(pc.y); gc = tanhf(pd.y);
        c.y = gf * po.y + gi * gc; st.y = gg * tanhf(c.y);
        gi = sigf(pa.z); gf = sigf(pb.z); gg = sigf(pc.z); gc = tanhf(pd.z);
        c.z = gf * po.z + gi * gc; st.z = gg * tanhf(c.z);
        gi = sigf(pa.w); gf = sigf(pb.w); gg = sigf(pc.w); gc = tanhf(pd.w);
        c.w = gf * po.w + gi * gc; st.w = gg * tanhf(c.w);
    }
    float4* o4 = reinterpret_cast<float4*>(out);
    const int Q = NELEM / 4;
    if (mode == 0) {
        o4[i] = c;
    } else if (mode == 1) {
        o4[i] = st; o4[Q + i] = c;
    } else {
        o4[i] = c; o4[Q + i] = st; o4[2 * Q + i] = c;
    }
}

// ---------------------------------------------------------------------------
extern "C" void kernel_launch(void* const* d_in, const int* in_sizes, int n_in,
                              void* d_out, int out_size)
{
    const float* X      = (const float*)d_in[0];
    const float* states = (const float*)d_in[1];
    const float* S0 = states;
    const float* S1 = states + NELEM;

    static bool attr_set = false;
    if (!attr_set) {
        cudaFuncSetAttribute(gate_gemm_tc,
                             cudaFuncAttributeMaxDynamicSharedMemorySize, SMEM_BYTES);
        attr_set = true;
    }

    WPtrs wp;
    wp.p[0] = (const float*)d_in[2];   // Wi
    wp.p[1] = (const float*)d_in[5];   // Wf
    wp.p[2] = (const float*)d_in[8];   // Wg
    wp.p[3] = (const float*)d_in[11];  // Wc
    wp.p[4] = (const float*)d_in[3];   // Ui
    wp.p[5] = (const float*)d_in[6];   // Uf
    wp.p[6] = (const float*)d_in[9];   // Ug
    wp.p[7] = (const float*)d_in[12];  // Uc

    convert_B<<<32768, 256>>>(wp);                 // 4*4096*2048 / 4 / 256
    convert_A<<<2048, 256>>>(X, S0);               // 512*4096 / 4 / 256

    dim3 grid(BQ / BM, HH / BN, 4);                // M fastest for L2 B reuse
    gate_gemm_tc<<<grid, 256, SMEM_BYTES>>>(
        (const float*)d_in[4], (const float*)d_in[7],
        (const float*)d_in[10], (const float*)d_in[13]);

    int mode;
    if (out_size == NELEM)          mode = 0;
    else if (out_size == 2 * NELEM) mode = 1;
    else                            mode = 2;
    lstm_elem<<<NELEM / 4 / 256, 256>>>(S1, (float*)d_out, mode);
}